// round 1
// baseline (speedup 1.0000x reference)
#include <cuda_runtime.h>
#include <math.h>

// Problem constants
#define BATCH 16
#define SEQ   1024
#define NTOK  (BATCH*SEQ)        // 16384
#define DMODEL 512
#define NHEAD  4
#define HDIM   128               // DMODEL/NHEAD
#define DMLP   1024
#define NBH    (BATCH*NHEAD)     // 64

// -------- scratch (no cudaMalloc allowed) --------
__device__ float g_x1n[NTOK*DMODEL];
__device__ float g_x2n[NTOK*DMODEL];
__device__ float g_q  [NTOK*DMODEL];
__device__ float g_k  [NTOK*DMODEL];
__device__ float g_v  [NTOK*DMODEL];
__device__ float g_ctx[NTOK*DMODEL];
__device__ float g_src1[NTOK*DMODEL];
__device__ float g_src2[NTOK*DMODEL];
__device__ float g_x  [NTOK*DMODEL];
__device__ float g_h1 [NTOK*DMLP];
__device__ float g_sc [(size_t)NBH*SEQ*SEQ];   // 256 MB score scratch

// ============================================================
// LayerNorm: one block per token row (D=512), 256 threads
// ============================================================
__global__ void ln_kernel(const float* __restrict__ x,
                          const float* __restrict__ g,
                          const float* __restrict__ b,
                          float* __restrict__ out) {
    int row = blockIdx.x;
    const float* xr = x + (size_t)row * DMODEL;
    float* orow = out + (size_t)row * DMODEL;
    int tid = threadIdx.x;                  // 256 threads
    float v0 = xr[tid], v1 = xr[tid + 256];

    __shared__ float sm[8];
    float s = v0 + v1;
    #pragma unroll
    for (int o = 16; o; o >>= 1) s += __shfl_xor_sync(0xffffffffu, s, o);
    if ((tid & 31) == 0) sm[tid >> 5] = s;
    __syncthreads();
    if (tid == 0) {
        float t = 0.f;
        #pragma unroll
        for (int i = 0; i < 8; i++) t += sm[i];
        sm[0] = t * (1.0f / DMODEL);
    }
    __syncthreads();
    float mean = sm[0];
    __syncthreads();

    float d0 = v0 - mean, d1 = v1 - mean;
    float q = d0 * d0 + d1 * d1;
    #pragma unroll
    for (int o = 16; o; o >>= 1) q += __shfl_xor_sync(0xffffffffu, q, o);
    if ((tid & 31) == 0) sm[tid >> 5] = q;
    __syncthreads();
    if (tid == 0) {
        float t = 0.f;
        #pragma unroll
        for (int i = 0; i < 8; i++) t += sm[i];
        sm[0] = rsqrtf(t * (1.0f / DMODEL) + 1e-6f);
    }
    __syncthreads();
    float rstd = sm[0];

    orow[tid]       = d0 * rstd * g[tid]       + b[tid];
    orow[tid + 256] = d1 * rstd * g[tid + 256] + b[tid + 256];
}

// ============================================================
// Generic SGEMM: C[M,Nc] = A[M,K] @ W[K,Nc] (+bias) (+gelu) (+add)
// BM=BN=64, BK=16, 256 threads, 4x4 microtile.
// Requires M%64==0, Nc%64==0, K%16==0 (true for all call sites).
// ============================================================
__global__ void sgemm_kernel(const float* __restrict__ A,
                             const float* __restrict__ W,
                             const float* __restrict__ bias,
                             const float* __restrict__ add,
                             float* __restrict__ C,
                             int M, int Nc, int K, int act) {
    int bm = blockIdx.y * 64, bn = blockIdx.x * 64;
    __shared__ float As[16][68];
    __shared__ float Bs[16][64];
    int tid = threadIdx.x;
    int ty = tid >> 4, tx = tid & 15;
    int lm = tid >> 2, lk = (tid & 3) * 4;     // A loader
    int kr = tid >> 4, nq = (tid & 15) * 4;    // B loader

    float acc[4][4] = {};
    for (int k0 = 0; k0 < K; k0 += 16) {
        float4 a = *(const float4*)&A[(size_t)(bm + lm) * K + k0 + lk];
        As[lk + 0][lm] = a.x; As[lk + 1][lm] = a.y;
        As[lk + 2][lm] = a.z; As[lk + 3][lm] = a.w;
        *(float4*)&Bs[kr][nq] = *(const float4*)&W[(size_t)(k0 + kr) * Nc + bn + nq];
        __syncthreads();
        #pragma unroll
        for (int kk = 0; kk < 16; kk++) {
            float av[4], bv[4];
            *(float4*)av = *(const float4*)&As[kk][ty * 4];
            *(float4*)bv = *(const float4*)&Bs[kk][tx * 4];
            #pragma unroll
            for (int i = 0; i < 4; i++)
                #pragma unroll
                for (int j = 0; j < 4; j++)
                    acc[i][j] = fmaf(av[i], bv[j], acc[i][j]);
        }
        __syncthreads();
    }

    #pragma unroll
    for (int i = 0; i < 4; i++) {
        int row = bm + ty * 4 + i;
        #pragma unroll
        for (int j = 0; j < 4; j++) {
            int col = bn + tx * 4 + j;
            float v = acc[i][j];
            if (bias) v += bias[col];
            if (act)  v = 0.5f * v * (1.0f + erff(v * 0.70710678118654752f));
            if (add)  v += add[(size_t)row * Nc + col];
            C[(size_t)row * Nc + col] = v;
        }
    }
}

// ============================================================
// Scores: S[bh,i,j] = scale * dot(Q[b,i,h,:], K[b,j,h,:]), hd=128
// ============================================================
__global__ void scores_kernel(const float* __restrict__ Q,
                              const float* __restrict__ Kmat,
                              float* __restrict__ S) {
    int bh = blockIdx.z, b = bh >> 2, h = bh & 3;
    int base = b * SEQ, hoff = h * HDIM;
    int bm = blockIdx.y * 64, bn = blockIdx.x * 64;
    __shared__ float As[16][68];
    __shared__ float Bs[16][68];
    int tid = threadIdx.x;
    int ty = tid >> 4, tx = tid & 15;
    int lm = tid >> 2, lk = (tid & 3) * 4;

    float acc[4][4] = {};
    for (int k0 = 0; k0 < HDIM; k0 += 16) {
        float4 a  = *(const float4*)&Q   [(size_t)(base + bm + lm) * DMODEL + hoff + k0 + lk];
        float4 bb = *(const float4*)&Kmat[(size_t)(base + bn + lm) * DMODEL + hoff + k0 + lk];
        As[lk + 0][lm] = a.x;  As[lk + 1][lm] = a.y;
        As[lk + 2][lm] = a.z;  As[lk + 3][lm] = a.w;
        Bs[lk + 0][lm] = bb.x; Bs[lk + 1][lm] = bb.y;
        Bs[lk + 2][lm] = bb.z; Bs[lk + 3][lm] = bb.w;
        __syncthreads();
        #pragma unroll
        for (int kk = 0; kk < 16; kk++) {
            float av[4], bv[4];
            *(float4*)av = *(const float4*)&As[kk][ty * 4];
            *(float4*)bv = *(const float4*)&Bs[kk][tx * 4];
            #pragma unroll
            for (int i = 0; i < 4; i++)
                #pragma unroll
                for (int j = 0; j < 4; j++)
                    acc[i][j] = fmaf(av[i], bv[j], acc[i][j]);
        }
        __syncthreads();
    }
    const float scale = 0.08838834764831845f;  // 1/sqrt(128)
    float* Sb = S + (size_t)bh * SEQ * SEQ;
    #pragma unroll
    for (int i = 0; i < 4; i++)
        #pragma unroll
        for (int j = 0; j < 4; j++)
            Sb[(size_t)(bm + ty * 4 + i) * SEQ + bn + tx * 4 + j] = acc[i][j] * scale;
}

// ============================================================
// Softmax over rows of 1024, in place. One block (256 thr) per row.
// ============================================================
__global__ void softmax_kernel(float* __restrict__ S) {
    float* r = S + (size_t)blockIdx.x * SEQ;
    int tid = threadIdx.x;
    float v[4];
    *(float4*)v = *(const float4*)&r[tid * 4];

    __shared__ float sm[8];
    float m = fmaxf(fmaxf(v[0], v[1]), fmaxf(v[2], v[3]));
    #pragma unroll
    for (int o = 16; o; o >>= 1) m = fmaxf(m, __shfl_xor_sync(0xffffffffu, m, o));
    if ((tid & 31) == 0) sm[tid >> 5] = m;
    __syncthreads();
    if (tid == 0) {
        float t = sm[0];
        #pragma unroll
        for (int i = 1; i < 8; i++) t = fmaxf(t, sm[i]);
        sm[0] = t;
    }
    __syncthreads();
    m = sm[0];
    __syncthreads();

    float s = 0.f;
    #pragma unroll
    for (int i = 0; i < 4; i++) { v[i] = __expf(v[i] - m); s += v[i]; }
    #pragma unroll
    for (int o = 16; o; o >>= 1) s += __shfl_xor_sync(0xffffffffu, s, o);
    if ((tid & 31) == 0) sm[tid >> 5] = s;
    __syncthreads();
    if (tid == 0) {
        float t = 0.f;
        #pragma unroll
        for (int i = 0; i < 8; i++) t += sm[i];
        sm[0] = 1.0f / t;
    }
    __syncthreads();
    float inv = sm[0];
    #pragma unroll
    for (int i = 0; i < 4; i++) v[i] *= inv;
    *(float4*)&r[tid * 4] = *(float4*)v;
}

// ============================================================
// PV: ctx[b,i,h,:] = sum_j P[bh,i,j] * V[b,j,h,:]
// ============================================================
__global__ void pv_kernel(const float* __restrict__ P,
                          const float* __restrict__ V,
                          float* __restrict__ O) {
    int bh = blockIdx.z, b = bh >> 2, h = bh & 3;
    int base = b * SEQ, hoff = h * HDIM;
    int bm = blockIdx.y * 64, bn = blockIdx.x * 64;  // bn in {0,64}
    const float* Pb = P + (size_t)bh * SEQ * SEQ;
    __shared__ float As[16][68];
    __shared__ float Bs[16][64];
    int tid = threadIdx.x;
    int ty = tid >> 4, tx = tid & 15;
    int lm = tid >> 2, lk = (tid & 3) * 4;
    int kr = tid >> 4, nq = (tid & 15) * 4;

    float acc[4][4] = {};
    for (int k0 = 0; k0 < SEQ; k0 += 16) {
        float4 a = *(const float4*)&Pb[(size_t)(bm + lm) * SEQ + k0 + lk];
        As[lk + 0][lm] = a.x; As[lk + 1][lm] = a.y;
        As[lk + 2][lm] = a.z; As[lk + 3][lm] = a.w;
        *(float4*)&Bs[kr][nq] =
            *(const float4*)&V[(size_t)(base + k0 + kr) * DMODEL + hoff + bn + nq];
        __syncthreads();
        #pragma unroll
        for (int kk = 0; kk < 16; kk++) {
            float av[4], bv[4];
            *(float4*)av = *(const float4*)&As[kk][ty * 4];
            *(float4*)bv = *(const float4*)&Bs[kk][tx * 4];
            #pragma unroll
            for (int i = 0; i < 4; i++)
                #pragma unroll
                for (int j = 0; j < 4; j++)
                    acc[i][j] = fmaf(av[i], bv[j], acc[i][j]);
        }
        __syncthreads();
    }
    #pragma unroll
    for (int i = 0; i < 4; i++)
        #pragma unroll
        for (int j = 0; j < 4; j++)
            O[(size_t)(base + bm + ty * 4 + i) * DMODEL + hoff + bn + tx * 4 + j] = acc[i][j];
}

// ============================================================
// Host orchestration
// ============================================================
static inline void run_sgemm(const float* A, const float* W, const float* bias,
                             const float* add, float* C, int M, int Nc, int K, int act) {
    dim3 grid(Nc / 64, M / 64);
    sgemm_kernel<<<grid, 256>>>(A, W, bias, add, C, M, Nc, K, act);
}

static void run_attention(const float* qin, const float* kvin,
                          const float* Wq, const float* bq,
                          const float* Wk, const float* bk,
                          const float* Wv, const float* bv,
                          const float* Wo, const float* bo,
                          const float* residual, float* out) {
    run_sgemm(qin,  Wq, bq, nullptr, g_q, NTOK, DMODEL, DMODEL, 0);
    run_sgemm(kvin, Wk, bk, nullptr, g_k, NTOK, DMODEL, DMODEL, 0);
    run_sgemm(kvin, Wv, bv, nullptr, g_v, NTOK, DMODEL, DMODEL, 0);

    dim3 gs(SEQ / 64, SEQ / 64, NBH);
    scores_kernel<<<gs, 256>>>(g_q, g_k, g_sc);
    softmax_kernel<<<NBH * SEQ, 256>>>(g_sc);
    dim3 gp(HDIM / 64, SEQ / 64, NBH);
    pv_kernel<<<gp, 256>>>(g_sc, g_v, g_ctx);

    run_sgemm(g_ctx, Wo, bo, residual, out, NTOK, DMODEL, DMODEL, 0);
}

extern "C" void kernel_launch(void* const* d_in, const int* in_sizes, int n_in,
                              void* d_out, int out_size) {
    const float* x1    = (const float*)d_in[0];
    const float* x2    = (const float*)d_in[1];
    const float* ln1_g = (const float*)d_in[2];
    const float* ln1_b = (const float*)d_in[3];
    const float* ln2_g = (const float*)d_in[4];
    const float* ln2_b = (const float*)d_in[5];
    const float* lnf_g = (const float*)d_in[6];
    const float* lnf_b = (const float*)d_in[7];
    const float* Wq1 = (const float*)d_in[8],  *bq1 = (const float*)d_in[9];
    const float* Wk1 = (const float*)d_in[10], *bk1 = (const float*)d_in[11];
    const float* Wv1 = (const float*)d_in[12], *bv1 = (const float*)d_in[13];
    const float* Wq2 = (const float*)d_in[14], *bq2 = (const float*)d_in[15];
    const float* Wk2 = (const float*)d_in[16], *bk2 = (const float*)d_in[17];
    const float* Wv2 = (const float*)d_in[18], *bv2 = (const float*)d_in[19];
    const float* Wq12 = (const float*)d_in[20], *bq12 = (const float*)d_in[21];
    const float* Wk12 = (const float*)d_in[22], *bk12 = (const float*)d_in[23];
    const float* Wv12 = (const float*)d_in[24], *bv12 = (const float*)d_in[25];
    const float* Wo  = (const float*)d_in[26], *bo = (const float*)d_in[27];
    const float* W1  = (const float*)d_in[28], *b1 = (const float*)d_in[29];
    const float* W2  = (const float*)d_in[30], *b2 = (const float*)d_in[31];
    float* out = (float*)d_out;

    float *x1n, *x2n, *src1, *src2, *xres, *h1, *xnorm;
    cudaGetSymbolAddress((void**)&x1n,  g_x1n);
    cudaGetSymbolAddress((void**)&x2n,  g_x2n);
    cudaGetSymbolAddress((void**)&src1, g_src1);
    cudaGetSymbolAddress((void**)&src2, g_src2);
    cudaGetSymbolAddress((void**)&xres, g_x);
    cudaGetSymbolAddress((void**)&h1,   g_h1);
    xnorm = x1n;  // reuse after streams are done with it

    // 1) pre-LN of both streams
    ln_kernel<<<NTOK, 256>>>(x1, ln1_g, ln1_b, x1n);
    ln_kernel<<<NTOK, 256>>>(x2, ln2_g, ln2_b, x2n);

    // 2) stream-1 self-attention (residual onto x1n)
    run_attention(x1n, x1n, Wq1, bq1, Wk1, bk1, Wv1, bv1, Wo, bo, x1n, src1);
    // 3) stream-2 self-attention (residual onto x2n)
    run_attention(x2n, x2n, Wq2, bq2, Wk2, bk2, Wv2, bv2, Wo, bo, x2n, src2);
    // 4) cross-attention: q from src1, k/v from src2; residual = original x1
    run_attention(src1, src2, Wq12, bq12, Wk12, bk12, Wv12, bv12, Wo, bo, x1, xres);

    // 5) final LN + MLP, residual onto xres
    ln_kernel<<<NTOK, 256>>>(xres, lnf_g, lnf_b, xnorm);
    run_sgemm(xnorm, W1, b1, nullptr, h1, NTOK, DMLP, DMODEL, 1);   // gelu
    run_sgemm(h1, W2, b2, xres, out, NTOK, DMODEL, DMLP, 0);        // + residual
    (void)in_sizes; (void)n_in; (void)out_size;
}

// round 2
// speedup vs baseline: 9.9786x; 9.9786x over previous
#include <cuda_runtime.h>
#include <math.h>

// Problem constants
#define BATCH 16
#define SEQ   1024
#define NTOK  (BATCH*SEQ)        // 16384
#define DMODEL 512
#define NHEAD  4
#define HDIM   128               // DMODEL/NHEAD
#define DMLP   1024
#define NBH    (BATCH*NHEAD)     // 64

#define BM 128
#define BN 128
#define BK 16

// -------- scratch (no cudaMalloc allowed) --------
__device__ float g_x1n[NTOK*DMODEL];
__device__ float g_x2n[NTOK*DMODEL];
__device__ float g_q  [NTOK*DMODEL];
__device__ float g_k  [NTOK*DMODEL];
__device__ float g_v  [NTOK*DMODEL];
__device__ float g_ctx[NTOK*DMODEL];
__device__ float g_src1[NTOK*DMODEL];
__device__ float g_src2[NTOK*DMODEL];
__device__ float g_x  [NTOK*DMODEL];
__device__ float g_h1 [NTOK*DMLP];
__device__ float g_sc [(size_t)NBH*SEQ*SEQ];   // 256 MB score scratch

// ============================================================
// LayerNorm: one block per token row (D=512), 256 threads
// ============================================================
__global__ void ln_kernel(const float* __restrict__ x,
                          const float* __restrict__ g,
                          const float* __restrict__ b,
                          float* __restrict__ out) {
    int row = blockIdx.x;
    const float* xr = x + (size_t)row * DMODEL;
    float* orow = out + (size_t)row * DMODEL;
    int tid = threadIdx.x;                  // 256 threads
    float v0 = xr[tid], v1 = xr[tid + 256];

    __shared__ float sm[8];
    float s = v0 + v1;
    #pragma unroll
    for (int o = 16; o; o >>= 1) s += __shfl_xor_sync(0xffffffffu, s, o);
    if ((tid & 31) == 0) sm[tid >> 5] = s;
    __syncthreads();
    if (tid == 0) {
        float t = 0.f;
        #pragma unroll
        for (int i = 0; i < 8; i++) t += sm[i];
        sm[0] = t * (1.0f / DMODEL);
    }
    __syncthreads();
    float mean = sm[0];
    __syncthreads();

    float d0 = v0 - mean, d1 = v1 - mean;
    float q = d0 * d0 + d1 * d1;
    #pragma unroll
    for (int o = 16; o; o >>= 1) q += __shfl_xor_sync(0xffffffffu, q, o);
    if ((tid & 31) == 0) sm[tid >> 5] = q;
    __syncthreads();
    if (tid == 0) {
        float t = 0.f;
        #pragma unroll
        for (int i = 0; i < 8; i++) t += sm[i];
        sm[0] = rsqrtf(t * (1.0f / DMODEL) + 1e-6f);
    }
    __syncthreads();
    float rstd = sm[0];

    orow[tid]       = d0 * rstd * g[tid]       + b[tid];
    orow[tid + 256] = d1 * rstd * g[tid + 256] + b[tid + 256];
}

// ============================================================
// High-throughput SGEMM: C = A @ B (or A @ B^T), 128x128x16 tiles,
// 256 threads, 8x8 microtile, double-buffered smem, reg-staged loads.
// Batched over blockIdx.z with (z>>2)*zs + (z&3)*hs offset scheme.
// Epilogue: *cscale, +bias, gelu, +add(residual, stride ldc).
// Requires M%128==0, N%128==0, K%16==0.
// ============================================================
template<int TRANSB>
__global__ void __launch_bounds__(256, 2)
gemm128(const float* __restrict__ A, const float* __restrict__ B,
        const float* __restrict__ bias, const float* __restrict__ add,
        float* __restrict__ C,
        int M, int N, int K,
        int lda, int ldb, int ldc,
        size_t zsA, size_t hsA, size_t zsB, size_t hsB,
        size_t zsC, size_t hsC,
        int act, float cscale)
{
    __shared__ float As[2][BK][BM + 4];
    __shared__ float Bs[2][BK][BN + 4];

    int z = blockIdx.z;
    const float* Az = A + (size_t)(z >> 2) * zsA + (size_t)(z & 3) * hsA;
    const float* Bz = B + (size_t)(z >> 2) * zsB + (size_t)(z & 3) * hsB;
    float*       Cz = C + (size_t)(z >> 2) * zsC + (size_t)(z & 3) * hsC;
    const float* Addz = add ? add + (size_t)(z >> 2) * zsC + (size_t)(z & 3) * hsC
                            : (const float*)0;

    int bm = blockIdx.y * BM, bn = blockIdx.x * BN;
    int tid = threadIdx.x;
    int ty = tid >> 4, tx = tid & 15;

    // A loader: 128 rows x 16 cols, 2 threads per row, transposed store
    int ar = tid >> 1, ac = (tid & 1) * 4;
    const float* Aptr = Az + (size_t)(bm + ar) * lda + ac;

    const float* Bptr;
    int br = 0, bc = 0;
    if (TRANSB) {
        Bptr = Bz + (size_t)(bn + ar) * ldb + ac;   // same shape as A loader
    } else {
        br = tid >> 4; bc = (tid & 15) * 4;         // 16 rows x 128 cols
        Bptr = Bz + (size_t)br * ldb + bn + bc;
    }

    float4 a0 = *(const float4*)(Aptr);
    float4 a1 = *(const float4*)(Aptr + 8);
    float4 b0, b1;
    if (TRANSB) { b0 = *(const float4*)(Bptr); b1 = *(const float4*)(Bptr + 8); }
    else        { b0 = *(const float4*)(Bptr); b1 = *(const float4*)(Bptr + 64); }

    // stage tile 0 into buf 0
    As[0][ac+0][ar] = a0.x; As[0][ac+1][ar] = a0.y;
    As[0][ac+2][ar] = a0.z; As[0][ac+3][ar] = a0.w;
    As[0][ac+8][ar] = a1.x; As[0][ac+9][ar] = a1.y;
    As[0][ac+10][ar] = a1.z; As[0][ac+11][ar] = a1.w;
    if (TRANSB) {
        Bs[0][ac+0][ar] = b0.x; Bs[0][ac+1][ar] = b0.y;
        Bs[0][ac+2][ar] = b0.z; Bs[0][ac+3][ar] = b0.w;
        Bs[0][ac+8][ar] = b1.x; Bs[0][ac+9][ar] = b1.y;
        Bs[0][ac+10][ar] = b1.z; Bs[0][ac+11][ar] = b1.w;
    } else {
        *(float4*)&Bs[0][br][bc]      = b0;
        *(float4*)&Bs[0][br][bc + 64] = b1;
    }
    __syncthreads();

    float acc[8][8] = {};
    int nk = K / BK;
    int buf = 0;
    for (int kt = 0; kt < nk; kt++) {
        if (kt + 1 < nk) {       // prefetch next tile into registers
            Aptr += BK;
            a0 = *(const float4*)(Aptr);
            a1 = *(const float4*)(Aptr + 8);
            if (TRANSB) {
                Bptr += BK;
                b0 = *(const float4*)(Bptr); b1 = *(const float4*)(Bptr + 8);
            } else {
                Bptr += (size_t)BK * ldb;
                b0 = *(const float4*)(Bptr); b1 = *(const float4*)(Bptr + 64);
            }
        }
        #pragma unroll
        for (int kk = 0; kk < BK; kk++) {
            float af[8], bf[8];
            *(float4*)&af[0] = *(const float4*)&As[buf][kk][ty * 8];
            *(float4*)&af[4] = *(const float4*)&As[buf][kk][ty * 8 + 4];
            *(float4*)&bf[0] = *(const float4*)&Bs[buf][kk][tx * 8];
            *(float4*)&bf[4] = *(const float4*)&Bs[buf][kk][tx * 8 + 4];
            #pragma unroll
            for (int i = 0; i < 8; i++)
                #pragma unroll
                for (int j = 0; j < 8; j++)
                    acc[i][j] = fmaf(af[i], bf[j], acc[i][j]);
        }
        if (kt + 1 < nk) {
            int nb = buf ^ 1;
            As[nb][ac+0][ar] = a0.x; As[nb][ac+1][ar] = a0.y;
            As[nb][ac+2][ar] = a0.z; As[nb][ac+3][ar] = a0.w;
            As[nb][ac+8][ar] = a1.x; As[nb][ac+9][ar] = a1.y;
            As[nb][ac+10][ar] = a1.z; As[nb][ac+11][ar] = a1.w;
            if (TRANSB) {
                Bs[nb][ac+0][ar] = b0.x; Bs[nb][ac+1][ar] = b0.y;
                Bs[nb][ac+2][ar] = b0.z; Bs[nb][ac+3][ar] = b0.w;
                Bs[nb][ac+8][ar] = b1.x; Bs[nb][ac+9][ar] = b1.y;
                Bs[nb][ac+10][ar] = b1.z; Bs[nb][ac+11][ar] = b1.w;
            } else {
                *(float4*)&Bs[nb][br][bc]      = b0;
                *(float4*)&Bs[nb][br][bc + 64] = b1;
            }
            __syncthreads();
            buf = nb;
        }
    }

    // epilogue
    int crow0 = bm + ty * 8;
    int ccol0 = bn + tx * 8;
    float bv[8];
    #pragma unroll
    for (int j = 0; j < 8; j++) bv[j] = bias ? bias[ccol0 + j] : 0.f;

    #pragma unroll
    for (int i = 0; i < 8; i++) {
        size_t off = (size_t)(crow0 + i) * ldc + ccol0;
        float v[8];
        #pragma unroll
        for (int j = 0; j < 8; j++) {
            float t = acc[i][j] * cscale + bv[j];
            if (act) t = 0.5f * t * (1.0f + erff(t * 0.70710678118654752f));
            v[j] = t;
        }
        if (Addz) {
            #pragma unroll
            for (int j = 0; j < 8; j++) v[j] += Addz[off + j];
        }
        *(float4*)&Cz[off]     = *(float4*)&v[0];
        *(float4*)&Cz[off + 4] = *(float4*)&v[4];
    }
}

// ============================================================
// Softmax over rows of 1024, in place. One block (256 thr) per row.
// ============================================================
__global__ void softmax_kernel(float* __restrict__ S) {
    float* r = S + (size_t)blockIdx.x * SEQ;
    int tid = threadIdx.x;
    float v[4];
    *(float4*)v = *(const float4*)&r[tid * 4];

    __shared__ float sm[8];
    float m = fmaxf(fmaxf(v[0], v[1]), fmaxf(v[2], v[3]));
    #pragma unroll
    for (int o = 16; o; o >>= 1) m = fmaxf(m, __shfl_xor_sync(0xffffffffu, m, o));
    if ((tid & 31) == 0) sm[tid >> 5] = m;
    __syncthreads();
    if (tid == 0) {
        float t = sm[0];
        #pragma unroll
        for (int i = 1; i < 8; i++) t = fmaxf(t, sm[i]);
        sm[0] = t;
    }
    __syncthreads();
    m = sm[0];
    __syncthreads();

    float s = 0.f;
    #pragma unroll
    for (int i = 0; i < 4; i++) { v[i] = __expf(v[i] - m); s += v[i]; }
    #pragma unroll
    for (int o = 16; o; o >>= 1) s += __shfl_xor_sync(0xffffffffu, s, o);
    if ((tid & 31) == 0) sm[tid >> 5] = s;
    __syncthreads();
    if (tid == 0) {
        float t = 0.f;
        #pragma unroll
        for (int i = 0; i < 8; i++) t += sm[i];
        sm[0] = 1.0f / t;
    }
    __syncthreads();
    float inv = sm[0];
    #pragma unroll
    for (int i = 0; i < 4; i++) v[i] *= inv;
    *(float4*)&r[tid * 4] = *(float4*)v;
}

// ============================================================
// Host orchestration
// ============================================================
static inline void run_proj(const float* A, const float* W, const float* bias,
                            const float* add, float* C, int M, int Nc, int K, int act) {
    dim3 grid(Nc / BN, M / BM, 1);
    gemm128<0><<<grid, 256>>>(A, W, bias, add, C, M, Nc, K,
                              K, Nc, Nc,
                              0, 0, 0, 0, 0, 0,
                              act, 1.0f);
}

static void run_attention(const float* qin, const float* kvin,
                          const float* Wq, const float* bq,
                          const float* Wk, const float* bk,
                          const float* Wv, const float* bv,
                          const float* Wo, const float* bo,
                          const float* residual, float* out,
                          float* q_s, float* k_s, float* v_s,
                          float* sc_s, float* ctx_s) {
    run_proj(qin,  Wq, bq, nullptr, q_s, NTOK, DMODEL, DMODEL, 0);
    run_proj(kvin, Wk, bk, nullptr, k_s, NTOK, DMODEL, DMODEL, 0);
    run_proj(kvin, Wv, bv, nullptr, v_s, NTOK, DMODEL, DMODEL, 0);

    // scores: S[bh] = scale * Q_bh @ K_bh^T
    {
        dim3 grid(SEQ / BN, SEQ / BM, NBH);
        gemm128<1><<<grid, 256>>>(q_s, k_s, nullptr, nullptr, sc_s,
                                  SEQ, SEQ, HDIM,
                                  DMODEL, DMODEL, SEQ,
                                  (size_t)SEQ * DMODEL, HDIM,
                                  (size_t)SEQ * DMODEL, HDIM,
                                  (size_t)4 * SEQ * SEQ, (size_t)SEQ * SEQ,
                                  0, 0.08838834764831845f);
    }
    softmax_kernel<<<NBH * SEQ, 256>>>(sc_s);
    // ctx[bh] = P_bh @ V_bh
    {
        dim3 grid(HDIM / BN, SEQ / BM, NBH);
        gemm128<0><<<grid, 256>>>(sc_s, v_s, nullptr, nullptr, ctx_s,
                                  SEQ, HDIM, SEQ,
                                  SEQ, DMODEL, DMODEL,
                                  (size_t)4 * SEQ * SEQ, (size_t)SEQ * SEQ,
                                  (size_t)SEQ * DMODEL, HDIM,
                                  (size_t)SEQ * DMODEL, HDIM,
                                  0, 1.0f);
    }
    run_proj(ctx_s, Wo, bo, residual, out, NTOK, DMODEL, DMODEL, 0);
}

extern "C" void kernel_launch(void* const* d_in, const int* in_sizes, int n_in,
                              void* d_out, int out_size) {
    const float* x1    = (const float*)d_in[0];
    const float* x2    = (const float*)d_in[1];
    const float* ln1_g = (const float*)d_in[2];
    const float* ln1_b = (const float*)d_in[3];
    const float* ln2_g = (const float*)d_in[4];
    const float* ln2_b = (const float*)d_in[5];
    const float* lnf_g = (const float*)d_in[6];
    const float* lnf_b = (const float*)d_in[7];
    const float* Wq1 = (const float*)d_in[8],  *bq1 = (const float*)d_in[9];
    const float* Wk1 = (const float*)d_in[10], *bk1 = (const float*)d_in[11];
    const float* Wv1 = (const float*)d_in[12], *bv1 = (const float*)d_in[13];
    const float* Wq2 = (const float*)d_in[14], *bq2 = (const float*)d_in[15];
    const float* Wk2 = (const float*)d_in[16], *bk2 = (const float*)d_in[17];
    const float* Wv2 = (const float*)d_in[18], *bv2 = (const float*)d_in[19];
    const float* Wq12 = (const float*)d_in[20], *bq12 = (const float*)d_in[21];
    const float* Wk12 = (const float*)d_in[22], *bk12 = (const float*)d_in[23];
    const float* Wv12 = (const float*)d_in[24], *bv12 = (const float*)d_in[25];
    const float* Wo  = (const float*)d_in[26], *bo = (const float*)d_in[27];
    const float* W1  = (const float*)d_in[28], *b1 = (const float*)d_in[29];
    const float* W2  = (const float*)d_in[30], *b2 = (const float*)d_in[31];
    float* out = (float*)d_out;

    float *x1n, *x2n, *src1, *src2, *xres, *h1, *qs, *ks, *vs, *scs, *ctxs;
    cudaGetSymbolAddress((void**)&x1n,  g_x1n);
    cudaGetSymbolAddress((void**)&x2n,  g_x2n);
    cudaGetSymbolAddress((void**)&src1, g_src1);
    cudaGetSymbolAddress((void**)&src2, g_src2);
    cudaGetSymbolAddress((void**)&xres, g_x);
    cudaGetSymbolAddress((void**)&h1,   g_h1);
    cudaGetSymbolAddress((void**)&qs,   g_q);
    cudaGetSymbolAddress((void**)&ks,   g_k);
    cudaGetSymbolAddress((void**)&vs,   g_v);
    cudaGetSymbolAddress((void**)&scs,  g_sc);
    cudaGetSymbolAddress((void**)&ctxs, g_ctx);
    float* xnorm = x1n;  // reuse after streams are done with it

    // 1) pre-LN of both streams
    ln_kernel<<<NTOK, 256>>>(x1, ln1_g, ln1_b, x1n);
    ln_kernel<<<NTOK, 256>>>(x2, ln2_g, ln2_b, x2n);

    // 2) stream-1 self-attention (residual onto x1n)
    run_attention(x1n, x1n, Wq1, bq1, Wk1, bk1, Wv1, bv1, Wo, bo, x1n, src1,
                  qs, ks, vs, scs, ctxs);
    // 3) stream-2 self-attention (residual onto x2n)
    run_attention(x2n, x2n, Wq2, bq2, Wk2, bk2, Wv2, bv2, Wo, bo, x2n, src2,
                  qs, ks, vs, scs, ctxs);
    // 4) cross-attention: q from src1, k/v from src2; residual = original x1
    run_attention(src1, src2, Wq12, bq12, Wk12, bk12, Wv12, bv12, Wo, bo, x1, xres,
                  qs, ks, vs, scs, ctxs);

    // 5) final LN + MLP, residual onto xres
    ln_kernel<<<NTOK, 256>>>(xres, lnf_g, lnf_b, xnorm);
    run_proj(xnorm, W1, b1, nullptr, h1, NTOK, DMLP, DMODEL, 1);   // gelu
    run_proj(h1, W2, b2, xres, out, NTOK, DMODEL, DMLP, 0);        // + residual
    (void)in_sizes; (void)n_in; (void)out_size;
}

// round 3
// speedup vs baseline: 18.3062x; 1.8346x over previous
#include <cuda_runtime.h>
#include <math.h>

// Problem constants
#define BATCH 16
#define SEQ   1024
#define NTOK  (BATCH*SEQ)        // 16384
#define DMODEL 512
#define NHEAD  4
#define HDIM   128               // DMODEL/NHEAD
#define DMLP   1024
#define NBH    (BATCH*NHEAD)     // 64

#define BM 128
#define BN 128
#define BK 16
#define SPITCH 132               // BM + 4 padding

// -------- scratch (no cudaMalloc allowed) --------
__device__ float g_x1n[NTOK*DMODEL];
__device__ float g_x2n[NTOK*DMODEL];
__device__ float g_q  [NTOK*DMODEL];
__device__ float g_k  [NTOK*DMODEL];
__device__ float g_v  [NTOK*DMODEL];
__device__ float g_ctx[NTOK*DMODEL];
__device__ float g_src1[NTOK*DMODEL];
__device__ float g_src2[NTOK*DMODEL];
__device__ float g_x  [NTOK*DMODEL];
__device__ float g_h1 [NTOK*DMLP];
__device__ float g_sc [(size_t)NBH*SEQ*SEQ];   // 256 MB score scratch

// fp32 -> tf32 (round to nearest) kept in float container
__device__ __forceinline__ float tf32r(float x) {
    unsigned r;
    asm("cvt.rna.tf32.f32 %0, %1;" : "=r"(r) : "f"(x));
    return __uint_as_float(r);
}

// ============================================================
// LayerNorm: one block per token row (D=512), 256 threads
// ============================================================
__global__ void ln_kernel(const float* __restrict__ x,
                          const float* __restrict__ g,
                          const float* __restrict__ b,
                          float* __restrict__ out) {
    int row = blockIdx.x;
    const float* xr = x + (size_t)row * DMODEL;
    float* orow = out + (size_t)row * DMODEL;
    int tid = threadIdx.x;
    float v0 = xr[tid], v1 = xr[tid + 256];

    __shared__ float sm[8];
    float s = v0 + v1;
    #pragma unroll
    for (int o = 16; o; o >>= 1) s += __shfl_xor_sync(0xffffffffu, s, o);
    if ((tid & 31) == 0) sm[tid >> 5] = s;
    __syncthreads();
    if (tid == 0) {
        float t = 0.f;
        #pragma unroll
        for (int i = 0; i < 8; i++) t += sm[i];
        sm[0] = t * (1.0f / DMODEL);
    }
    __syncthreads();
    float mean = sm[0];
    __syncthreads();

    float d0 = v0 - mean, d1 = v1 - mean;
    float q = d0 * d0 + d1 * d1;
    #pragma unroll
    for (int o = 16; o; o >>= 1) q += __shfl_xor_sync(0xffffffffu, q, o);
    if ((tid & 31) == 0) sm[tid >> 5] = q;
    __syncthreads();
    if (tid == 0) {
        float t = 0.f;
        #pragma unroll
        for (int i = 0; i < 8; i++) t += sm[i];
        sm[0] = rsqrtf(t * (1.0f / DMODEL) + 1e-6f);
    }
    __syncthreads();
    float rstd = sm[0];

    orow[tid]       = d0 * rstd * g[tid]       + b[tid];
    orow[tid + 256] = d1 * rstd * g[tid + 256] + b[tid + 256];
}

// ============================================================
// TF32 tensor-core GEMM: C = A @ B (or A @ B^T), 128x128x16 tiles,
// 256 threads = 8 warps (2 M x 4 N), warp tile 64x32, mma.m16n8k8.tf32.
// Double-buffered smem; fp32->tf32 conversion on smem store.
// Batched over blockIdx.z with (z>>2)*zs + (z&3)*hs offsets.
// Epilogue: *cscale, +bias, gelu, +add(residual).
// ============================================================
template<int TRANSB>
__global__ void __launch_bounds__(256, 2)
gemm_tc(const float* __restrict__ A, const float* __restrict__ B,
        const float* __restrict__ bias, const float* __restrict__ add,
        float* __restrict__ C,
        int M, int N, int K,
        int lda, int ldb, int ldc,
        size_t zsA, size_t hsA, size_t zsB, size_t hsB,
        size_t zsC, size_t hsC,
        int act, float cscale)
{
    __shared__ float As[2][BK][SPITCH];   // [k][m]
    __shared__ float Bs[2][BK][SPITCH];   // [k][n]

    int z = blockIdx.z;
    const float* Az = A + (size_t)(z >> 2) * zsA + (size_t)(z & 3) * hsA;
    const float* Bz = B + (size_t)(z >> 2) * zsB + (size_t)(z & 3) * hsB;
    float*       Cz = C + (size_t)(z >> 2) * zsC + (size_t)(z & 3) * hsC;
    const float* Addz = add ? add + (size_t)(z >> 2) * zsC + (size_t)(z & 3) * hsC
                            : (const float*)0;

    int bm = blockIdx.y * BM, bn = blockIdx.x * BN;
    int tid = threadIdx.x;
    int warp = tid >> 5, lane = tid & 31;
    int wm = warp >> 2, wn = warp & 3;        // warp tile origin (wm*64, wn*32)
    int gid = lane >> 2, tig = lane & 3;      // mma quad indexing

    // A loader: 128 rows x 16 cols, 2 threads/row, transposed store
    int ar = tid >> 1, ac = (tid & 1) * 4;
    const float* Aptr = Az + (size_t)(bm + ar) * lda + ac;

    const float* Bptr;
    int br = 0, bc = 0;
    if (TRANSB) {
        Bptr = Bz + (size_t)(bn + ar) * ldb + ac;
    } else {
        br = tid >> 4; bc = (tid & 15) * 4;
        Bptr = Bz + (size_t)br * ldb + bn + bc;
    }

    float4 a0 = *(const float4*)(Aptr);
    float4 a1 = *(const float4*)(Aptr + 8);
    float4 b0, b1;
    if (TRANSB) { b0 = *(const float4*)(Bptr); b1 = *(const float4*)(Bptr + 8); }
    else        { b0 = *(const float4*)(Bptr); b1 = *(const float4*)(Bptr + 64); }

    As[0][ac+0][ar] = tf32r(a0.x); As[0][ac+1][ar] = tf32r(a0.y);
    As[0][ac+2][ar] = tf32r(a0.z); As[0][ac+3][ar] = tf32r(a0.w);
    As[0][ac+8][ar] = tf32r(a1.x); As[0][ac+9][ar] = tf32r(a1.y);
    As[0][ac+10][ar] = tf32r(a1.z); As[0][ac+11][ar] = tf32r(a1.w);
    if (TRANSB) {
        Bs[0][ac+0][ar] = tf32r(b0.x); Bs[0][ac+1][ar] = tf32r(b0.y);
        Bs[0][ac+2][ar] = tf32r(b0.z); Bs[0][ac+3][ar] = tf32r(b0.w);
        Bs[0][ac+8][ar] = tf32r(b1.x); Bs[0][ac+9][ar] = tf32r(b1.y);
        Bs[0][ac+10][ar] = tf32r(b1.z); Bs[0][ac+11][ar] = tf32r(b1.w);
    } else {
        Bs[0][br][bc+0] = tf32r(b0.x); Bs[0][br][bc+1] = tf32r(b0.y);
        Bs[0][br][bc+2] = tf32r(b0.z); Bs[0][br][bc+3] = tf32r(b0.w);
        Bs[0][br][bc+64] = tf32r(b1.x); Bs[0][br][bc+65] = tf32r(b1.y);
        Bs[0][br][bc+66] = tf32r(b1.z); Bs[0][br][bc+67] = tf32r(b1.w);
    }
    __syncthreads();

    float acc[4][4][4];
    #pragma unroll
    for (int i = 0; i < 4; i++)
        #pragma unroll
        for (int j = 0; j < 4; j++)
            #pragma unroll
            for (int c = 0; c < 4; c++) acc[i][j][c] = 0.f;

    int nk = K / BK;
    int buf = 0;
    for (int kt = 0; kt < nk; kt++) {
        if (kt + 1 < nk) {       // prefetch next tile into registers
            Aptr += BK;
            a0 = *(const float4*)(Aptr);
            a1 = *(const float4*)(Aptr + 8);
            if (TRANSB) {
                Bptr += BK;
                b0 = *(const float4*)(Bptr); b1 = *(const float4*)(Bptr + 8);
            } else {
                Bptr += (size_t)BK * ldb;
                b0 = *(const float4*)(Bptr); b1 = *(const float4*)(Bptr + 64);
            }
        }
        #pragma unroll
        for (int ks = 0; ks < BK / 8; ks++) {
            int k0 = ks * 8;
            unsigned af[4][4], bf[4][2];
            #pragma unroll
            for (int ma = 0; ma < 4; ma++) {
                int m0 = wm * 64 + ma * 16;
                af[ma][0] = __float_as_uint(As[buf][k0 + tig][m0 + gid]);
                af[ma][1] = __float_as_uint(As[buf][k0 + tig][m0 + gid + 8]);
                af[ma][2] = __float_as_uint(As[buf][k0 + tig + 4][m0 + gid]);
                af[ma][3] = __float_as_uint(As[buf][k0 + tig + 4][m0 + gid + 8]);
            }
            #pragma unroll
            for (int nb = 0; nb < 4; nb++) {
                int n0 = wn * 32 + nb * 8;
                bf[nb][0] = __float_as_uint(Bs[buf][k0 + tig][n0 + gid]);
                bf[nb][1] = __float_as_uint(Bs[buf][k0 + tig + 4][n0 + gid]);
            }
            #pragma unroll
            for (int ma = 0; ma < 4; ma++)
                #pragma unroll
                for (int nb = 0; nb < 4; nb++) {
                    asm volatile(
                        "mma.sync.aligned.m16n8k8.row.col.f32.tf32.tf32.f32 "
                        "{%0,%1,%2,%3}, {%4,%5,%6,%7}, {%8,%9}, {%0,%1,%2,%3};\n"
                        : "+f"(acc[ma][nb][0]), "+f"(acc[ma][nb][1]),
                          "+f"(acc[ma][nb][2]), "+f"(acc[ma][nb][3])
                        : "r"(af[ma][0]), "r"(af[ma][1]), "r"(af[ma][2]), "r"(af[ma][3]),
                          "r"(bf[nb][0]), "r"(bf[nb][1]));
                }
        }
        if (kt + 1 < nk) {
            int nb2 = buf ^ 1;
            As[nb2][ac+0][ar] = tf32r(a0.x); As[nb2][ac+1][ar] = tf32r(a0.y);
            As[nb2][ac+2][ar] = tf32r(a0.z); As[nb2][ac+3][ar] = tf32r(a0.w);
            As[nb2][ac+8][ar] = tf32r(a1.x); As[nb2][ac+9][ar] = tf32r(a1.y);
            As[nb2][ac+10][ar] = tf32r(a1.z); As[nb2][ac+11][ar] = tf32r(a1.w);
            if (TRANSB) {
                Bs[nb2][ac+0][ar] = tf32r(b0.x); Bs[nb2][ac+1][ar] = tf32r(b0.y);
                Bs[nb2][ac+2][ar] = tf32r(b0.z); Bs[nb2][ac+3][ar] = tf32r(b0.w);
                Bs[nb2][ac+8][ar] = tf32r(b1.x); Bs[nb2][ac+9][ar] = tf32r(b1.y);
                Bs[nb2][ac+10][ar] = tf32r(b1.z); Bs[nb2][ac+11][ar] = tf32r(b1.w);
            } else {
                Bs[nb2][br][bc+0] = tf32r(b0.x); Bs[nb2][br][bc+1] = tf32r(b0.y);
                Bs[nb2][br][bc+2] = tf32r(b0.z); Bs[nb2][br][bc+3] = tf32r(b0.w);
                Bs[nb2][br][bc+64] = tf32r(b1.x); Bs[nb2][br][bc+65] = tf32r(b1.y);
                Bs[nb2][br][bc+66] = tf32r(b1.z); Bs[nb2][br][bc+67] = tf32r(b1.w);
            }
            __syncthreads();
            buf = nb2;
        }
    }

    // epilogue: each atom's thread owns (r, c),(r, c+1),(r+8, c),(r+8, c+1)
    #pragma unroll
    for (int ma = 0; ma < 4; ma++) {
        int r0 = bm + wm * 64 + ma * 16 + gid;
        #pragma unroll
        for (int nb = 0; nb < 4; nb++) {
            int c = bn + wn * 32 + nb * 8 + tig * 2;
            float bv0 = bias ? bias[c] : 0.f;
            float bv1 = bias ? bias[c + 1] : 0.f;
            #pragma unroll
            for (int half = 0; half < 2; half++) {
                int r = r0 + half * 8;
                float t0 = acc[ma][nb][half * 2 + 0] * cscale + bv0;
                float t1 = acc[ma][nb][half * 2 + 1] * cscale + bv1;
                if (act) {
                    t0 = 0.5f * t0 * (1.0f + erff(t0 * 0.70710678118654752f));
                    t1 = 0.5f * t1 * (1.0f + erff(t1 * 0.70710678118654752f));
                }
                size_t off = (size_t)r * ldc + c;
                if (Addz) { t0 += Addz[off]; t1 += Addz[off + 1]; }
                *(float2*)&Cz[off] = make_float2(t0, t1);
            }
        }
    }
}

// ============================================================
// Softmax over rows of 1024, in place. One block (256 thr) per row.
// ============================================================
__global__ void softmax_kernel(float* __restrict__ S) {
    float* r = S + (size_t)blockIdx.x * SEQ;
    int tid = threadIdx.x;
    float v[4];
    *(float4*)v = *(const float4*)&r[tid * 4];

    __shared__ float sm[8];
    float m = fmaxf(fmaxf(v[0], v[1]), fmaxf(v[2], v[3]));
    #pragma unroll
    for (int o = 16; o; o >>= 1) m = fmaxf(m, __shfl_xor_sync(0xffffffffu, m, o));
    if ((tid & 31) == 0) sm[tid >> 5] = m;
    __syncthreads();
    if (tid == 0) {
        float t = sm[0];
        #pragma unroll
        for (int i = 1; i < 8; i++) t = fmaxf(t, sm[i]);
        sm[0] = t;
    }
    __syncthreads();
    m = sm[0];
    __syncthreads();

    float s = 0.f;
    #pragma unroll
    for (int i = 0; i < 4; i++) { v[i] = __expf(v[i] - m); s += v[i]; }
    #pragma unroll
    for (int o = 16; o; o >>= 1) s += __shfl_xor_sync(0xffffffffu, s, o);
    if ((tid & 31) == 0) sm[tid >> 5] = s;
    __syncthreads();
    if (tid == 0) {
        float t = 0.f;
        #pragma unroll
        for (int i = 0; i < 8; i++) t += sm[i];
        sm[0] = 1.0f / t;
    }
    __syncthreads();
    float inv = sm[0];
    #pragma unroll
    for (int i = 0; i < 4; i++) v[i] *= inv;
    *(float4*)&r[tid * 4] = *(float4*)v;
}

// ============================================================
// Host orchestration
// ============================================================
static inline void run_proj(const float* A, const float* W, const float* bias,
                            const float* add, float* C, int M, int Nc, int K, int act) {
    dim3 grid(Nc / BN, M / BM, 1);
    gemm_tc<0><<<grid, 256>>>(A, W, bias, add, C, M, Nc, K,
                              K, Nc, Nc,
                              0, 0, 0, 0, 0, 0,
                              act, 1.0f);
}

static void run_attention(const float* qin, const float* kvin,
                          const float* Wq, const float* bq,
                          const float* Wk, const float* bk,
                          const float* Wv, const float* bv,
                          const float* Wo, const float* bo,
                          const float* residual, float* out,
                          float* q_s, float* k_s, float* v_s,
                          float* sc_s, float* ctx_s) {
    run_proj(qin,  Wq, bq, nullptr, q_s, NTOK, DMODEL, DMODEL, 0);
    run_proj(kvin, Wk, bk, nullptr, k_s, NTOK, DMODEL, DMODEL, 0);
    run_proj(kvin, Wv, bv, nullptr, v_s, NTOK, DMODEL, DMODEL, 0);

    // scores: S[bh] = scale * Q_bh @ K_bh^T
    {
        dim3 grid(SEQ / BN, SEQ / BM, NBH);
        gemm_tc<1><<<grid, 256>>>(q_s, k_s, nullptr, nullptr, sc_s,
                                  SEQ, SEQ, HDIM,
                                  DMODEL, DMODEL, SEQ,
                                  (size_t)SEQ * DMODEL, HDIM,
                                  (size_t)SEQ * DMODEL, HDIM,
                                  (size_t)4 * SEQ * SEQ, (size_t)SEQ * SEQ,
                                  0, 0.08838834764831845f);
    }
    softmax_kernel<<<NBH * SEQ, 256>>>(sc_s);
    // ctx[bh] = P_bh @ V_bh
    {
        dim3 grid(HDIM / BN, SEQ / BM, NBH);
        gemm_tc<0><<<grid, 256>>>(sc_s, v_s, nullptr, nullptr, ctx_s,
                                  SEQ, HDIM, SEQ,
                                  SEQ, DMODEL, DMODEL,
                                  (size_t)4 * SEQ * SEQ, (size_t)SEQ * SEQ,
                                  (size_t)SEQ * DMODEL, HDIM,
                                  (size_t)SEQ * DMODEL, HDIM,
                                  0, 1.0f);
    }
    run_proj(ctx_s, Wo, bo, residual, out, NTOK, DMODEL, DMODEL, 0);
}

extern "C" void kernel_launch(void* const* d_in, const int* in_sizes, int n_in,
                              void* d_out, int out_size) {
    const float* x1    = (const float*)d_in[0];
    const float* x2    = (const float*)d_in[1];
    const float* ln1_g = (const float*)d_in[2];
    const float* ln1_b = (const float*)d_in[3];
    const float* ln2_g = (const float*)d_in[4];
    const float* ln2_b = (const float*)d_in[5];
    const float* lnf_g = (const float*)d_in[6];
    const float* lnf_b = (const float*)d_in[7];
    const float* Wq1 = (const float*)d_in[8],  *bq1 = (const float*)d_in[9];
    const float* Wk1 = (const float*)d_in[10], *bk1 = (const float*)d_in[11];
    const float* Wv1 = (const float*)d_in[12], *bv1 = (const float*)d_in[13];
    const float* Wq2 = (const float*)d_in[14], *bq2 = (const float*)d_in[15];
    const float* Wk2 = (const float*)d_in[16], *bk2 = (const float*)d_in[17];
    const float* Wv2 = (const float*)d_in[18], *bv2 = (const float*)d_in[19];
    const float* Wq12 = (const float*)d_in[20], *bq12 = (const float*)d_in[21];
    const float* Wk12 = (const float*)d_in[22], *bk12 = (const float*)d_in[23];
    const float* Wv12 = (const float*)d_in[24], *bv12 = (const float*)d_in[25];
    const float* Wo  = (const float*)d_in[26], *bo = (const float*)d_in[27];
    const float* W1  = (const float*)d_in[28], *b1 = (const float*)d_in[29];
    const float* W2  = (const float*)d_in[30], *b2 = (const float*)d_in[31];
    float* out = (float*)d_out;

    float *x1n, *x2n, *src1, *src2, *xres, *h1, *qs, *ks, *vs, *scs, *ctxs;
    cudaGetSymbolAddress((void**)&x1n,  g_x1n);
    cudaGetSymbolAddress((void**)&x2n,  g_x2n);
    cudaGetSymbolAddress((void**)&src1, g_src1);
    cudaGetSymbolAddress((void**)&src2, g_src2);
    cudaGetSymbolAddress((void**)&xres, g_x);
    cudaGetSymbolAddress((void**)&h1,   g_h1);
    cudaGetSymbolAddress((void**)&qs,   g_q);
    cudaGetSymbolAddress((void**)&ks,   g_k);
    cudaGetSymbolAddress((void**)&vs,   g_v);
    cudaGetSymbolAddress((void**)&scs,  g_sc);
    cudaGetSymbolAddress((void**)&ctxs, g_ctx);
    float* xnorm = x1n;  // reuse after streams are done with it

    // 1) pre-LN of both streams
    ln_kernel<<<NTOK, 256>>>(x1, ln1_g, ln1_b, x1n);
    ln_kernel<<<NTOK, 256>>>(x2, ln2_g, ln2_b, x2n);

    // 2) stream-1 self-attention (residual onto x1n)
    run_attention(x1n, x1n, Wq1, bq1, Wk1, bk1, Wv1, bv1, Wo, bo, x1n, src1,
                  qs, ks, vs, scs, ctxs);
    // 3) stream-2 self-attention (residual onto x2n)
    run_attention(x2n, x2n, Wq2, bq2, Wk2, bk2, Wv2, bv2, Wo, bo, x2n, src2,
                  qs, ks, vs, scs, ctxs);
    // 4) cross-attention: q from src1, k/v from src2; residual = original x1
    run_attention(src1, src2, Wq12, bq12, Wk12, bk12, Wv12, bv12, Wo, bo, x1, xres,
                  qs, ks, vs, scs, ctxs);

    // 5) final LN + MLP, residual onto xres
    ln_kernel<<<NTOK, 256>>>(xres, lnf_g, lnf_b, xnorm);
    run_proj(xnorm, W1, b1, nullptr, h1, NTOK, DMLP, DMODEL, 1);   // gelu
    run_proj(h1, W2, b2, xres, out, NTOK, DMODEL, DMLP, 0);        // + residual
    (void)in_sizes; (void)n_in; (void)out_size;
}

// round 4
// speedup vs baseline: 21.2128x; 1.1588x over previous
#include <cuda_runtime.h>
#include <math.h>

// Problem constants
#define BATCH 16
#define SEQ   1024
#define NTOK  (BATCH*SEQ)        // 16384
#define DMODEL 512
#define NHEAD  4
#define HDIM   128
#define DMLP   1024
#define NBH    (BATCH*NHEAD)     // 64

#define BM 128
#define BN 128
#define BK 16
#define APITCH 20                // BM-side [m][k] pitch: conflict-free frag loads
#define BPITCH 136               // [k][n] pitch: conflict-free frag loads

// -------- scratch (no cudaMalloc allowed) --------
__device__ float g_x1n[NTOK*DMODEL];
__device__ float g_x2n[NTOK*DMODEL];
__device__ float g_q  [NTOK*DMODEL];
__device__ float g_k  [NTOK*DMODEL];
__device__ float g_v  [NTOK*DMODEL];
__device__ float g_ctx[NTOK*DMODEL];
__device__ float g_src1[NTOK*DMODEL];
__device__ float g_src2[NTOK*DMODEL];
__device__ float g_x  [NTOK*DMODEL];
__device__ float g_h1 [NTOK*DMLP];
__device__ float g_sc [(size_t)NBH*SEQ*SEQ];   // 256 MB score scratch
// rounded weights: 10x(512*512) + 512*1024 + 1024*512
__device__ float g_w  [10*DMODEL*DMODEL + 2*DMODEL*DMLP];

// fp32 -> tf32 (round to nearest) kept in float container
__device__ __forceinline__ float tf32r(float x) {
    unsigned r;
    asm("cvt.rna.tf32.f32 %0, %1;" : "=r"(r) : "f"(x));
    return __uint_as_float(r);
}

// ============================================================
// Round-copy (weights -> tf32-valued fp32 scratch)
// ============================================================
__global__ void round_copy(const float* __restrict__ in, float* __restrict__ out, int n) {
    int i = (blockIdx.x * 256 + threadIdx.x) * 4;
    if (i < n) {
        float4 v = *(const float4*)&in[i];
        v.x = tf32r(v.x); v.y = tf32r(v.y); v.z = tf32r(v.z); v.w = tf32r(v.w);
        *(float4*)&out[i] = v;
    }
}

// ============================================================
// LayerNorm: one block per token row (D=512), 256 threads.
// Output is tf32-rounded (it only feeds GEMMs / residual adds).
// ============================================================
__global__ void ln_kernel(const float* __restrict__ x,
                          const float* __restrict__ g,
                          const float* __restrict__ b,
                          float* __restrict__ out) {
    int row = blockIdx.x;
    const float* xr = x + (size_t)row * DMODEL;
    float* orow = out + (size_t)row * DMODEL;
    int tid = threadIdx.x;
    float v0 = xr[tid], v1 = xr[tid + 256];

    __shared__ float sm[8];
    float s = v0 + v1;
    #pragma unroll
    for (int o = 16; o; o >>= 1) s += __shfl_xor_sync(0xffffffffu, s, o);
    if ((tid & 31) == 0) sm[tid >> 5] = s;
    __syncthreads();
    if (tid == 0) {
        float t = 0.f;
        #pragma unroll
        for (int i = 0; i < 8; i++) t += sm[i];
        sm[0] = t * (1.0f / DMODEL);
    }
    __syncthreads();
    float mean = sm[0];
    __syncthreads();

    float d0 = v0 - mean, d1 = v1 - mean;
    float q = d0 * d0 + d1 * d1;
    #pragma unroll
    for (int o = 16; o; o >>= 1) q += __shfl_xor_sync(0xffffffffu, q, o);
    if ((tid & 31) == 0) sm[tid >> 5] = q;
    __syncthreads();
    if (tid == 0) {
        float t = 0.f;
        #pragma unroll
        for (int i = 0; i < 8; i++) t += sm[i];
        sm[0] = rsqrtf(t * (1.0f / DMODEL) + 1e-6f);
    }
    __syncthreads();
    float rstd = sm[0];

    orow[tid]       = tf32r(d0 * rstd * g[tid]       + b[tid]);
    orow[tid + 256] = tf32r(d1 * rstd * g[tid + 256] + b[tid + 256]);
}

// ============================================================
// TF32 tensor-core GEMM. Operands are PRE-ROUNDED to tf32 values.
// 128x128x16 tiles, 8 warps (2x4), warp tile 64x32, mma.m16n8k8.
// Conflict-free smem: As[m][k] pitch 20; Bs [k][n] pitch 136 (or [n][k] pitch 20).
// Reg-staged double buffer, one syncthreads per K-tile.
// ============================================================
template<int TRANSB>
__global__ void __launch_bounds__(256, 2)
gemm_tc(const float* __restrict__ A, const float* __restrict__ B,
        const float* __restrict__ bias, const float* __restrict__ add,
        float* __restrict__ C,
        int M, int N, int K,
        int lda, int ldb, int ldc,
        size_t zsA, size_t hsA, size_t zsB, size_t hsB,
        size_t zsC, size_t hsC,
        int act, float cscale, int round_out)
{
    constexpr int BSZ = TRANSB ? (BN * APITCH) : (BK * BPITCH);
    __shared__ float As[2][BM * APITCH];
    __shared__ float Bs[2][BSZ];

    int z = blockIdx.z;
    const float* Az = A + (size_t)(z >> 2) * zsA + (size_t)(z & 3) * hsA;
    const float* Bz = B + (size_t)(z >> 2) * zsB + (size_t)(z & 3) * hsB;
    float*       Cz = C + (size_t)(z >> 2) * zsC + (size_t)(z & 3) * hsC;
    const float* Addz = add ? add + (size_t)(z >> 2) * zsC + (size_t)(z & 3) * hsC
                            : (const float*)0;

    int bm = blockIdx.y * BM, bn = blockIdx.x * BN;
    int tid = threadIdx.x;
    int warp = tid >> 5, lane = tid & 31;
    int wm = warp >> 2, wn = warp & 3;        // warp tile (wm*64, wn*32)
    int gid = lane >> 2, tig = lane & 3;

    // A loader: thread -> row tid>>1, 8 cols at (tid&1)*8
    int arow = tid >> 1, acol = (tid & 1) * 8;
    const float* Aptr = Az + (size_t)(bm + arow) * lda + acol;
    int asw = arow * APITCH + acol;

    const float* Bptr;
    int bsw;
    if (TRANSB) {
        Bptr = Bz + (size_t)(bn + arow) * ldb + acol;
        bsw = arow * APITCH + acol;
    } else {
        int brow = tid >> 4, bcol = (tid & 15) * 8;
        Bptr = Bz + (size_t)brow * ldb + bn + bcol;
        bsw = brow * BPITCH + bcol;
    }

    float4 a0 = *(const float4*)(Aptr);
    float4 a1 = *(const float4*)(Aptr + 4);
    float4 b0 = *(const float4*)(Bptr);
    float4 b1 = *(const float4*)(Bptr + 4);

    *(float4*)&As[0][asw]     = a0;
    *(float4*)&As[0][asw + 4] = a1;
    *(float4*)&Bs[0][bsw]     = b0;
    *(float4*)&Bs[0][bsw + 4] = b1;
    __syncthreads();

    float acc[4][4][4];
    #pragma unroll
    for (int i = 0; i < 4; i++)
        #pragma unroll
        for (int j = 0; j < 4; j++)
            #pragma unroll
            for (int c = 0; c < 4; c++) acc[i][j][c] = 0.f;

    int nk = K / BK;
    int buf = 0;
    for (int kt = 0; kt < nk; kt++) {
        if (kt + 1 < nk) {       // prefetch next tile into registers
            Aptr += BK;
            a0 = *(const float4*)(Aptr);
            a1 = *(const float4*)(Aptr + 4);
            if (TRANSB) Bptr += BK; else Bptr += (size_t)BK * ldb;
            b0 = *(const float4*)(Bptr);
            b1 = *(const float4*)(Bptr + 4);
        }
        #pragma unroll
        for (int ks = 0; ks < 2; ks++) {
            int k0 = ks * 8;
            unsigned af[4][4], bf[4][2];
            #pragma unroll
            for (int ma = 0; ma < 4; ma++) {
                int mb = (wm * 64 + ma * 16 + gid) * APITCH + k0 + tig;
                af[ma][0] = __float_as_uint(As[buf][mb]);
                af[ma][1] = __float_as_uint(As[buf][mb + 8 * APITCH]);
                af[ma][2] = __float_as_uint(As[buf][mb + 4]);
                af[ma][3] = __float_as_uint(As[buf][mb + 8 * APITCH + 4]);
            }
            #pragma unroll
            for (int nb = 0; nb < 4; nb++) {
                int n0 = wn * 32 + nb * 8 + gid;
                if (TRANSB) {
                    int nbase = n0 * APITCH + k0 + tig;
                    bf[nb][0] = __float_as_uint(Bs[buf][nbase]);
                    bf[nb][1] = __float_as_uint(Bs[buf][nbase + 4]);
                } else {
                    int nbase = (k0 + tig) * BPITCH + n0;
                    bf[nb][0] = __float_as_uint(Bs[buf][nbase]);
                    bf[nb][1] = __float_as_uint(Bs[buf][nbase + 4 * BPITCH]);
                }
            }
            #pragma unroll
            for (int ma = 0; ma < 4; ma++)
                #pragma unroll
                for (int nb = 0; nb < 4; nb++) {
                    asm volatile(
                        "mma.sync.aligned.m16n8k8.row.col.f32.tf32.tf32.f32 "
                        "{%0,%1,%2,%3}, {%4,%5,%6,%7}, {%8,%9}, {%0,%1,%2,%3};\n"
                        : "+f"(acc[ma][nb][0]), "+f"(acc[ma][nb][1]),
                          "+f"(acc[ma][nb][2]), "+f"(acc[ma][nb][3])
                        : "r"(af[ma][0]), "r"(af[ma][1]), "r"(af[ma][2]), "r"(af[ma][3]),
                          "r"(bf[nb][0]), "r"(bf[nb][1]));
                }
        }
        if (kt + 1 < nk) {
            int nb2 = buf ^ 1;
            __syncthreads();   // all warps done reading buf^1 from prev iter
            *(float4*)&As[nb2][asw]     = a0;
            *(float4*)&As[nb2][asw + 4] = a1;
            *(float4*)&Bs[nb2][bsw]     = b0;
            *(float4*)&Bs[nb2][bsw + 4] = b1;
            __syncthreads();
            buf = nb2;
        }
    }

    // epilogue
    #pragma unroll
    for (int ma = 0; ma < 4; ma++) {
        int r0 = bm + wm * 64 + ma * 16 + gid;
        #pragma unroll
        for (int nb = 0; nb < 4; nb++) {
            int c = bn + wn * 32 + nb * 8 + tig * 2;
            float bv0 = bias ? bias[c] : 0.f;
            float bv1 = bias ? bias[c + 1] : 0.f;
            #pragma unroll
            for (int half = 0; half < 2; half++) {
                int r = r0 + half * 8;
                float t0 = acc[ma][nb][half * 2 + 0] * cscale + bv0;
                float t1 = acc[ma][nb][half * 2 + 1] * cscale + bv1;
                if (act) {
                    t0 = 0.5f * t0 * (1.0f + erff(t0 * 0.70710678118654752f));
                    t1 = 0.5f * t1 * (1.0f + erff(t1 * 0.70710678118654752f));
                }
                size_t off = (size_t)r * ldc + c;
                if (Addz) { t0 += Addz[off]; t1 += Addz[off + 1]; }
                if (round_out) { t0 = tf32r(t0); t1 = tf32r(t1); }
                *(float2*)&Cz[off] = make_float2(t0, t1);
            }
        }
    }
}

// ============================================================
// Softmax over rows of 1024, in place; output tf32-rounded (feeds PV GEMM).
// ============================================================
__global__ void softmax_kernel(float* __restrict__ S) {
    float* r = S + (size_t)blockIdx.x * SEQ;
    int tid = threadIdx.x;
    float v[4];
    *(float4*)v = *(const float4*)&r[tid * 4];

    __shared__ float sm[8];
    float m = fmaxf(fmaxf(v[0], v[1]), fmaxf(v[2], v[3]));
    #pragma unroll
    for (int o = 16; o; o >>= 1) m = fmaxf(m, __shfl_xor_sync(0xffffffffu, m, o));
    if ((tid & 31) == 0) sm[tid >> 5] = m;
    __syncthreads();
    if (tid == 0) {
        float t = sm[0];
        #pragma unroll
        for (int i = 1; i < 8; i++) t = fmaxf(t, sm[i]);
        sm[0] = t;
    }
    __syncthreads();
    m = sm[0];
    __syncthreads();

    float s = 0.f;
    #pragma unroll
    for (int i = 0; i < 4; i++) { v[i] = __expf(v[i] - m); s += v[i]; }
    #pragma unroll
    for (int o = 16; o; o >>= 1) s += __shfl_xor_sync(0xffffffffu, s, o);
    if ((tid & 31) == 0) sm[tid >> 5] = s;
    __syncthreads();
    if (tid == 0) {
        float t = 0.f;
        #pragma unroll
        for (int i = 0; i < 8; i++) t += sm[i];
        sm[0] = 1.0f / t;
    }
    __syncthreads();
    float inv = sm[0];
    #pragma unroll
    for (int i = 0; i < 4; i++) v[i] = tf32r(v[i] * inv);
    *(float4*)&r[tid * 4] = *(float4*)v;
}

// ============================================================
// Host orchestration
// ============================================================
static inline void run_proj(const float* A, const float* W, const float* bias,
                            const float* add, float* C, int M, int Nc, int K,
                            int act, int round_out) {
    dim3 grid(Nc / BN, M / BM, 1);
    gemm_tc<0><<<grid, 256>>>(A, W, bias, add, C, M, Nc, K,
                              K, Nc, Nc,
                              0, 0, 0, 0, 0, 0,
                              act, 1.0f, round_out);
}

static void run_attention(const float* qin, const float* kvin,
                          const float* Wq, const float* bq,
                          const float* Wk, const float* bk,
                          const float* Wv, const float* bv,
                          const float* Wo, const float* bo,
                          const float* residual, float* out, int round_src,
                          float* q_s, float* k_s, float* v_s,
                          float* sc_s, float* ctx_s) {
    run_proj(qin,  Wq, bq, nullptr, q_s, NTOK, DMODEL, DMODEL, 0, 1);
    run_proj(kvin, Wk, bk, nullptr, k_s, NTOK, DMODEL, DMODEL, 0, 1);
    run_proj(kvin, Wv, bv, nullptr, v_s, NTOK, DMODEL, DMODEL, 0, 1);

    // scores: S[bh] = scale * Q_bh @ K_bh^T
    {
        dim3 grid(SEQ / BN, SEQ / BM, NBH);
        gemm_tc<1><<<grid, 256>>>(q_s, k_s, nullptr, nullptr, sc_s,
                                  SEQ, SEQ, HDIM,
                                  DMODEL, DMODEL, SEQ,
                                  (size_t)SEQ * DMODEL, HDIM,
                                  (size_t)SEQ * DMODEL, HDIM,
                                  (size_t)4 * SEQ * SEQ, (size_t)SEQ * SEQ,
                                  0, 0.08838834764831845f, 0);
    }
    softmax_kernel<<<NBH * SEQ, 256>>>(sc_s);
    // ctx[bh] = P_bh @ V_bh
    {
        dim3 grid(HDIM / BN, SEQ / BM, NBH);
        gemm_tc<0><<<grid, 256>>>(sc_s, v_s, nullptr, nullptr, ctx_s,
                                  SEQ, HDIM, SEQ,
                                  SEQ, DMODEL, DMODEL,
                                  (size_t)4 * SEQ * SEQ, (size_t)SEQ * SEQ,
                                  (size_t)SEQ * DMODEL, HDIM,
                                  (size_t)SEQ * DMODEL, HDIM,
                                  0, 1.0f, 1);
    }
    run_proj(ctx_s, Wo, bo, residual, out, NTOK, DMODEL, DMODEL, 0, round_src);
}

extern "C" void kernel_launch(void* const* d_in, const int* in_sizes, int n_in,
                              void* d_out, int out_size) {
    const float* x1    = (const float*)d_in[0];
    const float* x2    = (const float*)d_in[1];
    const float* ln1_g = (const float*)d_in[2];
    const float* ln1_b = (const float*)d_in[3];
    const float* ln2_g = (const float*)d_in[4];
    const float* ln2_b = (const float*)d_in[5];
    const float* lnf_g = (const float*)d_in[6];
    const float* lnf_b = (const float*)d_in[7];
    const float* Wq1 = (const float*)d_in[8],  *bq1 = (const float*)d_in[9];
    const float* Wk1 = (const float*)d_in[10], *bk1 = (const float*)d_in[11];
    const float* Wv1 = (const float*)d_in[12], *bv1 = (const float*)d_in[13];
    const float* Wq2 = (const float*)d_in[14], *bq2 = (const float*)d_in[15];
    const float* Wk2 = (const float*)d_in[16], *bk2 = (const float*)d_in[17];
    const float* Wv2 = (const float*)d_in[18], *bv2 = (const float*)d_in[19];
    const float* Wq12 = (const float*)d_in[20], *bq12 = (const float*)d_in[21];
    const float* Wk12 = (const float*)d_in[22], *bk12 = (const float*)d_in[23];
    const float* Wv12 = (const float*)d_in[24], *bv12 = (const float*)d_in[25];
    const float* Wo  = (const float*)d_in[26], *bo = (const float*)d_in[27];
    const float* W1  = (const float*)d_in[28], *b1 = (const float*)d_in[29];
    const float* W2  = (const float*)d_in[30], *b2 = (const float*)d_in[31];
    float* out = (float*)d_out;

    float *x1n, *x2n, *src1, *src2, *xres, *h1, *qs, *ks, *vs, *scs, *ctxs, *wbuf;
    cudaGetSymbolAddress((void**)&x1n,  g_x1n);
    cudaGetSymbolAddress((void**)&x2n,  g_x2n);
    cudaGetSymbolAddress((void**)&src1, g_src1);
    cudaGetSymbolAddress((void**)&src2, g_src2);
    cudaGetSymbolAddress((void**)&xres, g_x);
    cudaGetSymbolAddress((void**)&h1,   g_h1);
    cudaGetSymbolAddress((void**)&qs,   g_q);
    cudaGetSymbolAddress((void**)&ks,   g_k);
    cudaGetSymbolAddress((void**)&vs,   g_v);
    cudaGetSymbolAddress((void**)&scs,  g_sc);
    cudaGetSymbolAddress((void**)&ctxs, g_ctx);
    cudaGetSymbolAddress((void**)&wbuf, g_w);
    float* xnorm = x1n;  // reuse after streams are done with it

    // 0) round all weights to tf32 values once
    const int WSQ = DMODEL * DMODEL;          // 262144
    const int WML = DMODEL * DMLP;            // 524288
    const float* wsrc[12] = {Wq1, Wk1, Wv1, Wq2, Wk2, Wv2, Wq12, Wk12, Wv12, Wo, W1, W2};
    float* wdst[12];
    {
        size_t off = 0;
        for (int i = 0; i < 12; i++) {
            wdst[i] = wbuf + off;
            int n = (i < 10) ? WSQ : WML;
            round_copy<<<n / 1024, 256>>>(wsrc[i], wdst[i], n);
            off += n;
        }
    }
    const float *rWq1 = wdst[0], *rWk1 = wdst[1], *rWv1 = wdst[2];
    const float *rWq2 = wdst[3], *rWk2 = wdst[4], *rWv2 = wdst[5];
    const float *rWq12 = wdst[6], *rWk12 = wdst[7], *rWv12 = wdst[8];
    const float *rWo = wdst[9], *rW1 = wdst[10], *rW2 = wdst[11];

    // 1) pre-LN of both streams (outputs tf32-rounded)
    ln_kernel<<<NTOK, 256>>>(x1, ln1_g, ln1_b, x1n);
    ln_kernel<<<NTOK, 256>>>(x2, ln2_g, ln2_b, x2n);

    // 2) stream-1 self-attention (residual onto x1n); src1 feeds GEMMs -> round
    run_attention(x1n, x1n, rWq1, bq1, rWk1, bk1, rWv1, bv1, rWo, bo, x1n, src1, 1,
                  qs, ks, vs, scs, ctxs);
    // 3) stream-2 self-attention
    run_attention(x2n, x2n, rWq2, bq2, rWk2, bk2, rWv2, bv2, rWo, bo, x2n, src2, 1,
                  qs, ks, vs, scs, ctxs);
    // 4) cross-attention: q from src1, k/v from src2; residual = original x1.
    //    xres only feeds LN + final residual -> keep full precision.
    run_attention(src1, src2, rWq12, bq12, rWk12, bk12, rWv12, bv12, rWo, bo, x1, xres, 0,
                  qs, ks, vs, scs, ctxs);

    // 5) final LN + MLP, residual onto xres
    ln_kernel<<<NTOK, 256>>>(xres, lnf_g, lnf_b, xnorm);
    run_proj(xnorm, rW1, b1, nullptr, h1, NTOK, DMLP, DMODEL, 1, 1);   // gelu, feeds W2
    run_proj(h1, rW2, b2, xres, out, NTOK, DMODEL, DMLP, 0, 0);        // final output
    (void)in_sizes; (void)n_in; (void)out_size;
}